// round 1
// baseline (speedup 1.0000x reference)
#include <cuda_runtime.h>
#include <cstdint>

#define NODES 32
#define NGRAPH 4096
#define FEAT 10
#define EPG 256                       // edges per graph (32 nodes * deg 8)
#define EDGES_TOTAL (NGRAPH * EPG)    // 1048576

#define HSTR 65     // h row stride (pad for conflict-free column reads)
#define XSTR 64     // xg row stride
#define CSTR 33     // cnt row stride
#define AI   33     // alpha i-stride
#define AH   1057   // alpha head-stride

struct Smem {
    float W[4352];            // weight buffer (<=4096) / alpha (4*1057=4228), reused
    float H[NODES * HSTR];    // h [32][64] padded
    float X[NODES * XSTR];    // xg [32][64]
    float C[NODES * CSTR];    // cnt [32][32] padded; also attention scratch
    float ES[128];            // e_src [head][j]
    float ED[128];            // e_dst [head][j]
    float AS[64];
    float AD[64];
    float B[64];
};

__device__ __forceinline__ float lrelu(float v, float s) { return v > 0.f ? v : v * s; }

template<int CIN, int H, int CHS>
__device__ void gat_layer(Smem& s,
                          const float* __restrict__ W, const float* __restrict__ as_,
                          const float* __restrict__ ad_, const float* __restrict__ b_,
                          int tid)
{
    constexpr int CH = 1 << CHS;
    __syncthreads();   // prior sX writes + alpha-region reads complete
    for (int t = tid; t < CIN * 64; t += 256) s.W[t] = W[t];
    if (tid < H * CH) { s.AS[tid] = as_[tid]; s.AD[tid] = ad_[tid]; }
    if (tid < 64) s.B[tid] = b_[tid];
    __syncthreads();

    // h = xg @ W   (h[i][k], 2048 outputs; thread: k = tid&63, rows i0+4r)
    {
        const int k = tid & 63;
        const int i0 = tid >> 6;
        float acc[8];
#pragma unroll
        for (int r = 0; r < 8; r++) acc[r] = 0.f;
#pragma unroll
        for (int m = 0; m < CIN; m++) {
            float w = s.W[m * 64 + k];
#pragma unroll
            for (int r = 0; r < 8; r++)
                acc[r] += s.X[(i0 + 4 * r) * XSTR + m] * w;
        }
#pragma unroll
        for (int r = 0; r < 8; r++) s.H[(i0 + 4 * r) * HSTR + k] = acc[r];
    }
    __syncthreads();

    // e_s[j][hd], e_d[j][hd]
    if (tid < 32 * H) {
        const int j = tid & 31, hd = tid >> 5;
        float as0 = 0.f, ad0 = 0.f;
#pragma unroll
        for (int c = 0; c < CH; c++) {
            float hv = s.H[j * HSTR + hd * CH + c];
            as0 += hv * s.AS[hd * CH + c];
            ad0 += hv * s.AD[hd * CH + c];
        }
        s.ES[hd * 32 + j] = as0;
        s.ED[hd * 32 + j] = ad0;
    }
    __syncthreads();

    // per (i, hd): dense masked softmax row -> alpha weights (incl. multiplicity)
    if (tid < 32 * H) {
        const int i = tid & 31, hd = tid >> 5;
        const float ed = s.ED[hd * 32 + i];
        float mx = -1e30f;
#pragma unroll
        for (int j = 0; j < 32; j++) {
            float c = s.C[i * CSTR + j];
            float ev = lrelu(s.ES[hd * 32 + j] + ed, 0.2f);
            if (c > 0.f && ev > mx) mx = ev;
        }
        float w[32];
        float denom = 0.f;
#pragma unroll
        for (int j = 0; j < 32; j++) {
            float c = s.C[i * CSTR + j];
            float ev = lrelu(s.ES[hd * 32 + j] + ed, 0.2f);
            float ex = c * __expf(ev - mx);     // c==0 -> contributes 0
            w[j] = ex;
            denom += ex;
        }
        float inv = 1.f / (denom + 1e-16f);
#pragma unroll
        for (int j = 0; j < 32; j++)
            s.W[hd * AH + i * AI + j] = w[j] * inv;   // alpha lives in W buffer
    }
    __syncthreads();

    // out[i][k] = sum_j alpha[hd(k)][i][j] * h[j][k]; + bias; lrelu(0.01) -> xg
    {
        const int k = tid & 63;
        const int i0 = tid >> 6;
        const int hd = k >> CHS;
        float acc[8];
#pragma unroll
        for (int r = 0; r < 8; r++) acc[r] = 0.f;
#pragma unroll
        for (int j = 0; j < 32; j++) {
            float hv = s.H[j * HSTR + k];
#pragma unroll
            for (int r = 0; r < 8; r++)
                acc[r] += s.W[hd * AH + (i0 + 4 * r) * AI + j] * hv;
        }
        float bb = s.B[k];
#pragma unroll
        for (int r = 0; r < 8; r++)
            s.X[(i0 + 4 * r) * XSTR + k] = lrelu(acc[r] + bb, 0.01f);
    }
}

__global__ __launch_bounds__(256) void gnn_kernel(
    const float* __restrict__ x, const int* __restrict__ ei,
    const float* __restrict__ Wq, const float* __restrict__ Wk, const float* __restrict__ Wv,
    const float* __restrict__ W1, const float* __restrict__ a1s, const float* __restrict__ a1d, const float* __restrict__ b1,
    const float* __restrict__ W2, const float* __restrict__ a2s, const float* __restrict__ a2d, const float* __restrict__ b2,
    const float* __restrict__ W3, const float* __restrict__ a3s, const float* __restrict__ a3d, const float* __restrict__ b3,
    const float* __restrict__ W4, const float* __restrict__ a4s, const float* __restrict__ a4d, const float* __restrict__ b4,
    const float* __restrict__ fcW, const float* __restrict__ fcb,
    float* __restrict__ out, int out_half)
{
    __shared__ Smem s;
    const int tid = threadIdx.x;
    const int g = blockIdx.x;

    // edge_index dtype probe: int32 -> last word = last dst (>=131040, nonzero);
    // int64 -> last word = high half of src[E-1] = 0.
    const bool is64 = (ei[2 * (size_t)EDGES_TOTAL - 1] == 0);

    // ---------------- Attention layer ----------------
    for (int t = tid; t < 1024; t += 256) {
        s.W[t]        = Wq[t];
        s.W[1024 + t] = Wk[t];
        s.W[2048 + t] = Wv[t];
    }
    // att_in[s][i] = x[g*32+i][s]  -> s.X[s*32+i]
    for (int t = tid; t < 320; t += 256) {
        int si = t >> 5, ii = t & 31;
        s.X[t] = x[(size_t)(g * 32 + ii) * FEAT + si];
    }
    __syncthreads();
    // Q,K,V [10][32] -> s.H[0..959]
    for (int t = tid; t < 960; t += 256) {
        int which = t / 320, r = t - which * 320;
        int si = r >> 5, c = r & 31;
        const float* w = s.W + which * 1024;
        float acc = 0.f;
#pragma unroll
        for (int ii = 0; ii < 32; ii++) acc += s.X[si * 32 + ii] * w[ii * 32 + c];
        s.H[t] = acc;
    }
    __syncthreads();
    // scores[s][t] -> s.C[0..99]
    if (tid < 100) {
        int si = tid / 10, ti = tid - si * 10;
        float acc = 0.f;
#pragma unroll
        for (int c = 0; c < 32; c++) acc += s.H[si * 32 + c] * s.H[320 + ti * 32 + c];
        s.C[tid] = acc;
    }
    __syncthreads();
    if (tid < 10) {
        float mx = -1e30f;
#pragma unroll
        for (int t2 = 0; t2 < 10; t2++) mx = fmaxf(mx, s.C[tid * 10 + t2]);
        float e[10], sum = 0.f;
#pragma unroll
        for (int t2 = 0; t2 < 10; t2++) { e[t2] = __expf(s.C[tid * 10 + t2] - mx); sum += e[t2]; }
        float inv = 1.f / sum;
#pragma unroll
        for (int t2 = 0; t2 < 10; t2++) s.C[tid * 10 + t2] = e[t2] * inv;
    }
    __syncthreads();
    // out[s][i] = sum_t alpha[s][t] V[t][i]; scatter to xg[i][s]
    for (int t = tid; t < 320; t += 256) {
        int si = t >> 5, ii = t & 31;
        float acc = 0.f;
#pragma unroll
        for (int t2 = 0; t2 < 10; t2++) acc += s.C[si * 10 + t2] * s.H[640 + t2 * 32 + ii];
        s.X[ii * XSTR + si] = acc;
    }
    __syncthreads();

    // ---------------- Build per-graph multiplicity matrix (shared by all 4 layers) ----
    for (int t = tid; t < NODES * CSTR; t += 256) s.C[t] = 0.f;
    __syncthreads();
    {
        size_t eg = (size_t)g * EPG + tid;   // 256 threads, 256 edges
        int srcv, dstv;
        if (is64) {
            srcv = ei[2 * eg];
            dstv = ei[2 * ((size_t)EDGES_TOTAL + eg)];
        } else {
            srcv = ei[eg];
            dstv = ei[(size_t)EDGES_TOTAL + eg];
        }
        int sl = srcv - g * 32, dl = dstv - g * 32;
        atomicAdd(&s.C[dl * CSTR + sl], 1.0f);
        if (tid < 32) atomicAdd(&s.C[tid * CSTR + tid], 1.0f);  // self-loops
    }

    // ---------------- GAT stack ----------------
    gat_layer<10, 4, 4>(s, W1, a1s, a1d, b1, tid);
    gat_layer<64, 4, 4>(s, W2, a2s, a2d, b2, tid);
    gat_layer<64, 4, 4>(s, W3, a3s, a3d, b3, tid);
    gat_layer<64, 1, 6>(s, W4, a4s, a4d, b4, tid);
    __syncthreads();

    // ---------------- Mean pool + FC + softmax ----------------
    if (tid < 64) {
        float acc = 0.f;
#pragma unroll
        for (int i = 0; i < 32; i++) acc += s.X[i * XSTR + tid];
        s.H[tid] = acc * (1.f / 32.f);
    }
    __syncthreads();
    if (tid < 2) {
        float acc = fcb[tid];
#pragma unroll
        for (int k2 = 0; k2 < 64; k2++) acc += s.H[k2] * fcW[k2 * 2 + tid];
        s.C[512 + tid] = acc;
    }
    __syncthreads();
    if (tid == 0) {
        float l0 = s.C[512], l1 = s.C[513];
        out[g * 2 + 0] = l0;
        out[g * 2 + 1] = l1;
        float mx = fmaxf(l0, l1);
        float e0 = __expf(l0 - mx), e1 = __expf(l1 - mx);
        float inv = 1.f / (e0 + e1);
        out[out_half + g * 2 + 0] = e0 * inv;
        out[out_half + g * 2 + 1] = e1 * inv;
    }
}

extern "C" void kernel_launch(void* const* d_in, const int* in_sizes, int n_in,
                              void* d_out, int out_size)
{
    const float* x   = (const float*)d_in[0];
    const int*   ei  = (const int*)d_in[1];
    // d_in[2] = batch (unused; derivable)
    const float* Wq  = (const float*)d_in[3];
    const float* Wk  = (const float*)d_in[4];
    const float* Wv  = (const float*)d_in[5];
    const float* W1  = (const float*)d_in[6];
    const float* a1s = (const float*)d_in[7];
    const float* a1d = (const float*)d_in[8];
    const float* b1  = (const float*)d_in[9];
    const float* W2  = (const float*)d_in[10];
    const float* a2s = (const float*)d_in[11];
    const float* a2d = (const float*)d_in[12];
    const float* b2  = (const float*)d_in[13];
    const float* W3  = (const float*)d_in[14];
    const float* a3s = (const float*)d_in[15];
    const float* a3d = (const float*)d_in[16];
    const float* b3  = (const float*)d_in[17];
    const float* W4  = (const float*)d_in[18];
    const float* a4s = (const float*)d_in[19];
    const float* a4d = (const float*)d_in[20];
    const float* b4  = (const float*)d_in[21];
    const float* fcW = (const float*)d_in[22];
    const float* fcb = (const float*)d_in[23];

    gnn_kernel<<<NGRAPH, 256>>>(x, ei, Wq, Wk, Wv,
                                W1, a1s, a1d, b1,
                                W2, a2s, a2d, b2,
                                W3, a3s, a3d, b3,
                                W4, a4s, a4d, b4,
                                fcW, fcb,
                                (float*)d_out, out_size / 2);
}

// round 4
// speedup vs baseline: 1.4198x; 1.4198x over previous
#include <cuda_runtime.h>
#include <cstdint>

#define NODES 32
#define NGRAPH 4096
#define FEAT 10
#define EPG 256
#define EDGES_TOTAL (NGRAPH * EPG)

#define XSTR 68     // X row stride (4-aligned, conflict-free for our lane map)
#define WTSTR 68    // Wt row stride
#define HTSTR 36    // Ht row stride
#define ASTR 36     // alpha row stride
#define AHD 1152    // alpha head stride (32*36)
#define CSTR 33

typedef unsigned long long ull;

struct Smem {
    float WA[4608];   // Wt[k][m] (64x68) then alpha[hd][i][36]; also Wq/Wk/Wv^T in attention
    float Ht[2304];   // h transposed [k][i] (64x36); also Q/K/V in attention; pool scratch
    float X[2176];    // activations [i][m] (32x68)
    float C[1056];    // multiplicity [i][j] (32x33); att_in during attention
    float ES[128];    // e_src / attention scores
    float ED[128];
    float AS[64], AD[64], B[64];
};

__device__ __forceinline__ void fma2(ull& acc, ull a, ull b) {
    asm("fma.rn.f32x2 %0, %1, %2, %0;" : "+l"(acc) : "l"(a), "l"(b));
}
__device__ __forceinline__ float red2(ull v) {
    float lo, hi;
    asm("mov.b64 {%0,%1}, %2;" : "=f"(lo), "=f"(hi) : "l"(v));
    return lo + hi;
}
__device__ __forceinline__ ulonglong2 ld2(const float* p) {
    return *(const ulonglong2*)p;
}
__device__ __forceinline__ float lrelu(float v, float s) { return v > 0.f ? v : v * s; }

template<int CIN, int CINP, int H>
__device__ void gat_layer(Smem& s,
                          const float* __restrict__ W, const float* __restrict__ as_,
                          const float* __restrict__ ad_, const float* __restrict__ b_,
                          int tid)
{
    const int lane = tid & 31;
    const int w    = tid >> 5;
    const int dp   = lane & 7;       // 0..7
    const int gp   = lane >> 3;      // 0..3
    const int cq   = w & 3;          // col quarter (== head for H=4)
    const int rh   = w >> 2;         // row half
    const int k0   = cq * 16 + dp;
    const int k1   = k0 + 8;
    const int ib   = rh * 16 + gp;   // rows ib + 4r

    __syncthreads();   // prior X writes & prior alpha reads complete

    // Load transposed weights Wt[k][m] (zero-padded to CINP), attention vecs, bias
    for (int t = tid; t < 64 * CINP; t += 256) {
        int k = t & 63, m = t >> 6;
        s.WA[k * WTSTR + m] = (m < CIN) ? W[m * 64 + k] : 0.f;
    }
    if (tid < 64) { s.AS[tid] = as_[tid]; s.AD[tid] = ad_[tid]; s.B[tid] = b_[tid]; }
    __syncthreads();

    // ---- mm1: Ht[k][i] = sum_m X[i][m] * Wt[k][m] ----
    {
        ull acc[4][2] = {};
        const float* wt0 = &s.WA[k0 * WTSTR];
        const float* wt1 = &s.WA[k1 * WTSTR];
#pragma unroll
        for (int mg = 0; mg < CINP; mg += 4) {
            ulonglong2 w0 = ld2(wt0 + mg), w1 = ld2(wt1 + mg);
#pragma unroll
            for (int r = 0; r < 4; r++) {
                ulonglong2 xv = ld2(&s.X[(ib + 4 * r) * XSTR + mg]);
                fma2(acc[r][0], xv.x, w0.x); fma2(acc[r][0], xv.y, w0.y);
                fma2(acc[r][1], xv.x, w1.x); fma2(acc[r][1], xv.y, w1.y);
            }
        }
#pragma unroll
        for (int r = 0; r < 4; r++) {
            s.Ht[k0 * HTSTR + ib + 4 * r] = red2(acc[r][0]);
            s.Ht[k1 * HTSTR + ib + 4 * r] = red2(acc[r][1]);
        }
    }
    __syncthreads();

    // ---- attention scalars: e_s[j], e_d[j] per head (or partials for H=1) ----
    if (tid < 128) {
        const int j = tid & 31, seg = tid >> 5;
        const int c0 = seg * 16;
        float as0 = 0.f, ad0 = 0.f;
#pragma unroll
        for (int c = 0; c < 16; c++) {
            float hv = s.Ht[(c0 + c) * HTSTR + j];
            as0 += hv * s.AS[c0 + c];
            ad0 += hv * s.AD[c0 + c];
        }
        s.ES[seg * 32 + j] = as0;
        s.ED[seg * 32 + j] = ad0;
    }
    __syncthreads();
    if (H == 1) {
        if (tid < 32) {
            s.ES[tid] = s.ES[tid] + s.ES[32 + tid] + s.ES[64 + tid] + s.ES[96 + tid];
            s.ED[tid] = s.ED[tid] + s.ED[32 + tid] + s.ED[64 + tid] + s.ED[96 + tid];
        }
        __syncthreads();
    }

    // ---- masked softmax per (i, head), multiplicity-weighted; alpha -> WA ----
    if (tid < 32 * H) {
        const int i = tid & 31, hd = tid >> 5;
        const float edi = s.ED[hd * 32 + i];
        const float* esr = &s.ES[hd * 32];
        const float* crow = &s.C[i * CSTR];
        float ev[32];
        float mx = -1e30f;
#pragma unroll
        for (int j = 0; j < 32; j++) {
            float e = lrelu(esr[j] + edi, 0.2f);
            ev[j] = e;
            if (crow[j] > 0.f && e > mx) mx = e;
        }
        float den = 0.f;
#pragma unroll
        for (int j = 0; j < 32; j++) {
            float wv = crow[j] * __expf(ev[j] - mx);
            ev[j] = wv; den += wv;
        }
        float inv = 1.f / (den + 1e-16f);
        float* arow = &s.WA[hd * AHD + i * ASTR];
#pragma unroll
        for (int jg = 0; jg < 32; jg += 4) {
            *(float4*)&arow[jg] = make_float4(ev[jg] * inv, ev[jg + 1] * inv,
                                              ev[jg + 2] * inv, ev[jg + 3] * inv);
        }
    }
    __syncthreads();

    // ---- mm2: X[i][k] = lrelu( sum_j alpha[hd][i][j] * Ht[k][j] + b[k], 0.01 ) ----
    {
        const int hd = (H == 4) ? cq : 0;
        ull acc[4][2] = {};
        const float* h0 = &s.Ht[k0 * HTSTR];
        const float* h1 = &s.Ht[k1 * HTSTR];
#pragma unroll
        for (int jg = 0; jg < 32; jg += 4) {
            ulonglong2 hv0 = ld2(h0 + jg), hv1 = ld2(h1 + jg);
#pragma unroll
            for (int r = 0; r < 4; r++) {
                ulonglong2 av = ld2(&s.WA[hd * AHD + (ib + 4 * r) * ASTR + jg]);
                fma2(acc[r][0], av.x, hv0.x); fma2(acc[r][0], av.y, hv0.y);
                fma2(acc[r][1], av.x, hv1.x); fma2(acc[r][1], av.y, hv1.y);
            }
        }
        const float b0 = s.B[k0], b1 = s.B[k1];
#pragma unroll
        for (int r = 0; r < 4; r++) {
            s.X[(ib + 4 * r) * XSTR + k0] = lrelu(red2(acc[r][0]) + b0, 0.01f);
            s.X[(ib + 4 * r) * XSTR + k1] = lrelu(red2(acc[r][1]) + b1, 0.01f);
        }
    }
}

__global__ __launch_bounds__(256, 3) void gnn_kernel(
    const float* __restrict__ x, const int* __restrict__ ei,
    const float* __restrict__ Wq, const float* __restrict__ Wk, const float* __restrict__ Wv,
    const float* __restrict__ W1, const float* __restrict__ a1s, const float* __restrict__ a1d, const float* __restrict__ b1,
    const float* __restrict__ W2, const float* __restrict__ a2s, const float* __restrict__ a2d, const float* __restrict__ b2,
    const float* __restrict__ W3, const float* __restrict__ a3s, const float* __restrict__ a3d, const float* __restrict__ b3,
    const float* __restrict__ W4, const float* __restrict__ a4s, const float* __restrict__ a4d, const float* __restrict__ b4,
    const float* __restrict__ fcW, const float* __restrict__ fcb,
    float* __restrict__ out, int out_half)
{
    __shared__ Smem s;
    const int tid = threadIdx.x;
    const int g = blockIdx.x;

    const bool is64 = (ei[2 * (size_t)EDGES_TOTAL - 1] == 0);

    // ---------------- Attention layer ----------------
    // P1: Wq/Wk/Wv transposed into WA ([c][i], stride 36); att_in[s][i] -> C
    for (int t = tid; t < 3072; t += 256) {
        int which = t >> 10, r = t & 1023;
        int i = r >> 5, c = r & 31;
        const float* Wsrc = (which == 0) ? Wq : (which == 1) ? Wk : Wv;
        s.WA[which * 1152 + c * 36 + i] = Wsrc[r];
    }
    for (int t = tid; t < 320; t += 256) {
        int si = t >> 5, ii = t & 31;
        s.C[si * 32 + ii] = x[(size_t)(g * 32 + ii) * FEAT + si];
    }
    __syncthreads();

    // P2: Q,K,V [s][c] stride 36 -> Ht at 0/360/720
    for (int o = tid; o < 960; o += 256) {
        int which = o / 320, r = o - which * 320;
        int si = r >> 5, c = r & 31;
        const float* wt = &s.WA[which * 1152 + c * 36];
        const float* at = &s.C[si * 32];
        ull acc = 0;
#pragma unroll
        for (int ig = 0; ig < 32; ig += 4) {
            ulonglong2 a2 = ld2(at + ig), w2 = ld2(wt + ig);
            fma2(acc, a2.x, w2.x); fma2(acc, a2.y, w2.y);
        }
        s.Ht[which * 360 + si * 36 + c] = red2(acc);
    }
    __syncthreads();

    // P3: scores [s][t] -> ES; zero C
    for (int t = tid; t < NODES * CSTR; t += 256) s.C[t] = 0.f;
    if (tid < 100) {
        int si = tid / 10, ti = tid - si * 10;
        ull acc = 0;
#pragma unroll
        for (int cg = 0; cg < 32; cg += 4) {
            ulonglong2 q2 = ld2(&s.Ht[si * 36 + cg]);
            ulonglong2 k2 = ld2(&s.Ht[360 + ti * 36 + cg]);
            fma2(acc, q2.x, k2.x); fma2(acc, q2.y, k2.y);
        }
        s.ES[si * 10 + ti] = red2(acc);
    }
    __syncthreads();

    // P4: edge multiplicity build (atomics into C) + attention row softmax
    {
        size_t eg = (size_t)g * EPG + tid;
        int srcv, dstv;
        if (is64) {
            srcv = ei[2 * eg];
            dstv = ei[2 * ((size_t)EDGES_TOTAL + eg)];
        } else {
            srcv = ei[eg];
            dstv = ei[(size_t)EDGES_TOTAL + eg];
        }
        int sl = srcv - g * 32, dl = dstv - g * 32;
        atomicAdd(&s.C[dl * CSTR + sl], 1.0f);
        if (tid < 32) atomicAdd(&s.C[tid * CSTR + tid], 1.0f);  // self-loops
    }
    if (tid < 10) {
        float mx = -1e30f;
#pragma unroll
        for (int t2 = 0; t2 < 10; t2++) mx = fmaxf(mx, s.ES[tid * 10 + t2]);
        float e[10], sum = 0.f;
#pragma unroll
        for (int t2 = 0; t2 < 10; t2++) { e[t2] = __expf(s.ES[tid * 10 + t2] - mx); sum += e[t2]; }
        float inv = 1.f / sum;
#pragma unroll
        for (int t2 = 0; t2 < 10; t2++) s.ES[tid * 10 + t2] = e[t2] * inv;
    }
    __syncthreads();

    // P5: att out[s][i] -> X[i][s]; zero pad cols 10,11
    for (int t = tid; t < 320; t += 256) {
        int si = t >> 5, ii = t & 31;
        float acc = 0.f;
#pragma unroll
        for (int t2 = 0; t2 < 10; t2++)
            acc += s.ES[si * 10 + t2] * s.Ht[720 + t2 * 36 + ii];
        s.X[ii * XSTR + si] = acc;
    }
    if (tid < 64) s.X[(tid & 31) * XSTR + 10 + (tid >> 5)] = 0.f;
    // (sync happens at gat_layer entry)

    // ---------------- GAT stack ----------------
    gat_layer<10, 12, 4>(s, W1, a1s, a1d, b1, tid);
    gat_layer<64, 64, 4>(s, W2, a2s, a2d, b2, tid);
    gat_layer<64, 64, 4>(s, W3, a3s, a3d, b3, tid);
    gat_layer<64, 64, 1>(s, W4, a4s, a4d, b4, tid);
    __syncthreads();

    // ---------------- Mean pool + FC + softmax ----------------
    if (tid < 64) {
        float acc = 0.f;
#pragma unroll
        for (int i = 0; i < 32; i++) acc += s.X[i * XSTR + tid];
        s.Ht[tid] = acc * (1.f / 32.f);
    }
    __syncthreads();
    if (tid < 2) {
        float acc = fcb[tid];
#pragma unroll
        for (int k2 = 0; k2 < 64; k2++) acc += s.Ht[k2] * fcW[k2 * 2 + tid];
        s.ED[tid] = acc;
    }
    __syncthreads();
    if (tid == 0) {
        float l0 = s.ED[0], l1 = s.ED[1];
        out[g * 2 + 0] = l0;
        out[g * 2 + 1] = l1;
        float mx = fmaxf(l0, l1);
        float e0 = __expf(l0 - mx), e1 = __expf(l1 - mx);
        float inv = 1.f / (e0 + e1);
        out[out_half + g * 2 + 0] = e0 * inv;
        out[out_half + g * 2 + 1] = e1 * inv;
    }
}

extern "C" void kernel_launch(void* const* d_in, const int* in_sizes, int n_in,
                              void* d_out, int out_size)
{
    const float* x   = (const float*)d_in[0];
    const int*   ei  = (const int*)d_in[1];
    const float* Wq  = (const float*)d_in[3];
    const float* Wk  = (const float*)d_in[4];
    const float* Wv  = (const float*)d_in[5];
    const float* W1  = (const float*)d_in[6];
    const float* a1s = (const float*)d_in[7];
    const float* a1d = (const float*)d_in[8];
    const float* b1  = (const float*)d_in[9];
    const float* W2  = (const float*)d_in[10];
    const float* a2s = (const float*)d_in[11];
    const float* a2d = (const float*)d_in[12];
    const float* b2  = (const float*)d_in[13];
    const float* W3  = (const float*)d_in[14];
    const float* a3s = (const float*)d_in[15];
    const float* a3d = (const float*)d_in[16];
    const float* b3  = (const float*)d_in[17];
    const float* W4  = (const float*)d_in[18];
    const float* a4s = (const float*)d_in[19];
    const float* a4d = (const float*)d_in[20];
    const float* b4  = (const float*)d_in[21];
    const float* fcW = (const float*)d_in[22];
    const float* fcb = (const float*)d_in[23];

    gnn_kernel<<<NGRAPH, 256>>>(x, ei, Wq, Wk, Wv,
                                W1, a1s, a1d, b1,
                                W2, a2s, a2d, b2,
                                W3, a3s, a3d, b3,
                                W4, a4s, a4d, b4,
                                fcW, fcb,
                                (float*)d_out, out_size / 2);
}

// round 7
// speedup vs baseline: 1.5093x; 1.0630x over previous
#include <cuda_runtime.h>
#include <cstdint>

#define NODES 32
#define NGRAPH 4096
#define FEAT 10
#define EPG 256
#define EDGES_TOTAL (NGRAPH * EPG)

#define XSTR 68     // X row stride
#define WTSTR 68    // Wt row stride (GAT weights, transposed)
#define HTSTR 40    // GAT Ht row stride (conflict-free for a/g lane map)
#define QSTR 36     // attention Q/K/V row stride
#define ASTR 36     // alpha row stride
#define AHD 1152    // alpha head stride (32*36)
#define CSTR 33

typedef unsigned long long ull;

struct Smem {
    float WA[4608];   // Wt[k][m] 64x68 -> alpha[hd][i][36]; attn: Wq/Wk/Wv^T (stride QSTR)
    float Ht[2560];   // GAT h^T [k][i] 64x40; attn: Q/K/V [s][c] stride 36; pool scratch
    float X[2176];    // activations [i][m] 32x68
    float C[1056];    // multiplicity [i][j] 32x33
    float ES[128];
    float ED[128];
    float AS[64], AD[64], B[64];
};

__device__ __forceinline__ void fma2(ull& acc, ull a, ull b) {
    asm("fma.rn.f32x2 %0, %1, %2, %0;" : "+l"(acc) : "l"(a), "l"(b));
}
__device__ __forceinline__ float red2(ull v) {
    float lo, hi;
    asm("mov.b64 {%0,%1}, %2;" : "=f"(lo), "=f"(hi) : "l"(v));
    return lo + hi;
}
__device__ __forceinline__ ulonglong2 ld2(const float* p) {
    return *(const ulonglong2*)p;
}
__device__ __forceinline__ float lrelu(float v, float s) { return v > 0.f ? v : v * s; }

template<int CIN, int CINP, int H>
__device__ void gat_layer(Smem& s,
                          const float* __restrict__ W, const float* __restrict__ as_,
                          const float* __restrict__ ad_, const float* __restrict__ b_,
                          int tid)
{
    __syncthreads();   // prior X writes / alpha reads complete

    // ---- Stage Wt[k][m] conflict-free: lane = k-low(8) x m-low(4) -> banks 4k+m all distinct
    {
        const int kk = (tid & 7) + 8 * (tid >> 5);     // 0..63
        const int m0 = (tid >> 3) & 3;
#pragma unroll
        for (int p = 0; p < CINP / 4; p++) {
            int m = m0 + 4 * p;
            s.WA[kk * WTSTR + m] = (m < CIN) ? W[m * 64 + kk] : 0.f;
        }
    }
    if (tid < 64) { s.AS[tid] = as_[tid]; s.AD[tid] = ad_[tid]; s.B[tid] = b_[tid]; }
    __syncthreads();

    const int a  = tid & 3;          // k-low
    const int g2 = (tid >> 2) & 7;   // row-low
    const int w  = tid >> 5;         // warp (0..3 active for mm)

    // ---- mm1: Ht[k][i] = sum_m X[i][m] * Wt[k][m]   (128 threads, 4x4 tiles)
    if (tid < 128) {
        ull acc[4][4] = {};
#pragma unroll
        for (int mg = 0; mg < CINP; mg += 4) {
            ulonglong2 wv[4];
#pragma unroll
            for (int q = 0; q < 4; q++)
                wv[q] = ld2(&s.WA[(16 * w + a + 4 * q) * WTSTR + mg]);
#pragma unroll
            for (int r = 0; r < 4; r++) {
                ulonglong2 xv = ld2(&s.X[(g2 + 8 * r) * XSTR + mg]);
#pragma unroll
                for (int q = 0; q < 4; q++) {
                    fma2(acc[r][q], xv.x, wv[q].x);
                    fma2(acc[r][q], xv.y, wv[q].y);
                }
            }
        }
#pragma unroll
        for (int r = 0; r < 4; r++)
#pragma unroll
            for (int q = 0; q < 4; q++)
                s.Ht[(16 * w + a + 4 * q) * HTSTR + g2 + 8 * r] = red2(acc[r][q]);
    }
    __syncthreads();

    // ---- e_s[j], e_d[j] per head (partials for H=1)
    if (tid < 128) {
        const int j = tid & 31, seg = tid >> 5;
        const int c0 = seg * 16;
        float as0 = 0.f, ad0 = 0.f;
#pragma unroll
        for (int c = 0; c < 16; c++) {
            float hv = s.Ht[(c0 + c) * HTSTR + j];
            as0 += hv * s.AS[c0 + c];
            ad0 += hv * s.AD[c0 + c];
        }
        s.ES[seg * 32 + j] = as0;
        s.ED[seg * 32 + j] = ad0;
    }
    __syncthreads();
    if (H == 1) {
        if (tid < 32) {
            s.ES[tid] = s.ES[tid] + s.ES[32 + tid] + s.ES[64 + tid] + s.ES[96 + tid];
            s.ED[tid] = s.ED[tid] + s.ED[32 + tid] + s.ED[64 + tid] + s.ED[96 + tid];
        }
        __syncthreads();
    }

    // ---- masked, multiplicity-weighted softmax; alpha -> WA (Wt dead)
    if (tid < 32 * H) {
        const int i = tid & 31, hd = tid >> 5;
        const float edi = s.ED[hd * 32 + i];
        const float* esr = &s.ES[hd * 32];
        const float* crow = &s.C[i * CSTR];
        float ev[32];
        float mx = -1e30f;
#pragma unroll
        for (int j = 0; j < 32; j++) {
            float e = lrelu(esr[j] + edi, 0.2f);
            ev[j] = e;
            if (crow[j] > 0.f && e > mx) mx = e;
        }
        float den = 0.f;
#pragma unroll
        for (int j = 0; j < 32; j++) {
            float wv = crow[j] * __expf(ev[j] - mx);
            ev[j] = wv; den += wv;
        }
        float inv = 1.f / (den + 1e-16f);
        float* arow = &s.WA[hd * AHD + i * ASTR];
#pragma unroll
        for (int jg = 0; jg < 32; jg += 4)
            *(float4*)&arow[jg] = make_float4(ev[jg] * inv, ev[jg + 1] * inv,
                                              ev[jg + 2] * inv, ev[jg + 3] * inv);
    }
    __syncthreads();

    // ---- mm2: X[i][k] = lrelu( sum_j alpha[hd][i][j]*Ht[k][j] + b[k] )  (128 thr, 4x4)
    if (tid < 128) {
        const int hd = (H == 4) ? w : 0;
        ull acc[4][4] = {};
#pragma unroll
        for (int jg = 0; jg < 32; jg += 4) {
            ulonglong2 hv[4];
#pragma unroll
            for (int q = 0; q < 4; q++)
                hv[q] = ld2(&s.Ht[(16 * w + a + 4 * q) * HTSTR + jg]);
#pragma unroll
            for (int r = 0; r < 4; r++) {
                ulonglong2 av = ld2(&s.WA[hd * AHD + (g2 + 8 * r) * ASTR + jg]);
#pragma unroll
                for (int q = 0; q < 4; q++) {
                    fma2(acc[r][q], av.x, hv[q].x);
                    fma2(acc[r][q], av.y, hv[q].y);
                }
            }
        }
#pragma unroll
        for (int r = 0; r < 4; r++)
#pragma unroll
            for (int q = 0; q < 4; q++) {
                int k = 16 * w + a + 4 * q;
                s.X[(g2 + 8 * r) * XSTR + k] = lrelu(red2(acc[r][q]) + s.B[k], 0.01f);
            }
    }
}

__global__ __launch_bounds__(256, 3) void gnn_kernel(
    const float* __restrict__ x, const int* __restrict__ ei,
    const float* __restrict__ Wq, const float* __restrict__ Wk, const float* __restrict__ Wv,
    const float* __restrict__ W1, const float* __restrict__ a1s, const float* __restrict__ a1d, const float* __restrict__ b1,
    const float* __restrict__ W2, const float* __restrict__ a2s, const float* __restrict__ a2d, const float* __restrict__ b2,
    const float* __restrict__ W3, const float* __restrict__ a3s, const float* __restrict__ a3d, const float* __restrict__ b3,
    const float* __restrict__ W4, const float* __restrict__ a4s, const float* __restrict__ a4d, const float* __restrict__ b4,
    const float* __restrict__ fcW, const float* __restrict__ fcb,
    float* __restrict__ out, int out_half)
{
    __shared__ Smem s;
    const int tid = threadIdx.x;
    const int g = blockIdx.x;

    const bool is64 = (ei[2 * (size_t)EDGES_TOTAL - 1] == 0);

    // ---------------- Attention layer ----------------
    // P1: Wq/Wk/Wv transposed into WA [c][i] stride QSTR, conflict-free:
    //     lanes vary i-low(4) x c-low(8) -> banks 4c+i all distinct.
    {
        const int il = tid & 3;
        const int cl = (tid >> 2) & 7;
        const int ih = (tid >> 5) & 3;
        const int ch = (tid >> 7) & 1;
#pragma unroll
        for (int e = 0; e < 12; e++) {
            int which = e >> 2, f = e & 3;
            int i = il + 4 * ih + 16 * (f & 1);
            int c = cl + 8 * ch + 16 * (f >> 1);
            const float* Wsrc = (which == 0) ? Wq : (which == 1) ? Wk : Wv;
            s.WA[which * 1280 + c * QSTR + i] = Wsrc[i * 32 + c];
        }
    }
    for (int t = tid; t < 320; t += 256) {
        int si = t >> 5, ii = t & 31;
        s.C[si * 32 + ii] = x[(size_t)(g * 32 + ii) * FEAT + si];
    }
    __syncthreads();

    // P2: Q,K,V [s][c] stride 36 -> Ht at 0/360/720
    for (int o = tid; o < 960; o += 256) {
        int which = o / 320, r = o - which * 320;
        int si = r >> 5, c = r & 31;
        const float* wt = &s.WA[which * 1280 + c * QSTR];
        const float* at = &s.C[si * 32];
        ull acc = 0;
#pragma unroll
        for (int ig = 0; ig < 32; ig += 4) {
            ulonglong2 a2 = ld2(at + ig), w2 = ld2(wt + ig);
            fma2(acc, a2.x, w2.x); fma2(acc, a2.y, w2.y);
        }
        s.Ht[which * 360 + si * 36 + c] = red2(acc);
    }
    __syncthreads();

    // P3: scores [s][t] -> ES; zero C
    for (int t = tid; t < NODES * CSTR; t += 256) s.C[t] = 0.f;
    if (tid < 100) {
        int si = tid / 10, ti = tid - si * 10;
        ull acc = 0;
#pragma unroll
        for (int cg = 0; cg < 32; cg += 4) {
            ulonglong2 q2 = ld2(&s.Ht[si * 36 + cg]);
            ulonglong2 k2 = ld2(&s.Ht[360 + ti * 36 + cg]);
            fma2(acc, q2.x, k2.x); fma2(acc, q2.y, k2.y);
        }
        s.ES[si * 10 + ti] = red2(acc);
    }
    __syncthreads();

    // P4: multiplicity matrix + attention row softmax
    {
        size_t eg = (size_t)g * EPG + tid;
        int srcv, dstv;
        if (is64) {
            srcv = ei[2 * eg];
            dstv = ei[2 * ((size_t)EDGES_TOTAL + eg)];
        } else {
            srcv = ei[eg];
            dstv = ei[(size_t)EDGES_TOTAL + eg];
        }
        int sl = srcv - g * 32, dl = dstv - g * 32;
        atomicAdd(&s.C[dl * CSTR + sl], 1.0f);
        if (tid < 32) atomicAdd(&s.C[tid * CSTR + tid], 1.0f);  // self-loops
    }
    if (tid < 10) {
        float mx = -1e30f;
#pragma unroll
        for (int t2 = 0; t2 < 10; t2++) mx = fmaxf(mx, s.ES[tid * 10 + t2]);
        float e[10], sum = 0.f;
#pragma unroll
        for (int t2 = 0; t2 < 10; t2++) { e[t2] = __expf(s.ES[tid * 10 + t2] - mx); sum += e[t2]; }
        float inv = 1.f / sum;
#pragma unroll
        for (int t2 = 0; t2 < 10; t2++) s.ES[tid * 10 + t2] = e[t2] * inv;
    }
    __syncthreads();

    // P5: att out[s][i] -> X[i][s]; zero pad cols 10,11
    for (int t = tid; t < 320; t += 256) {
        int si = t >> 5, ii = t & 31;
        float acc = 0.f;
#pragma unroll
        for (int t2 = 0; t2 < 10; t2++)
            acc += s.ES[si * 10 + t2] * s.Ht[720 + t2 * 36 + ii];
        s.X[ii * XSTR + si] = acc;
    }
    if (tid < 64) s.X[(tid & 31) * XSTR + 10 + (tid >> 5)] = 0.f;

    // ---------------- GAT stack ----------------
    gat_layer<10, 12, 4>(s, W1, a1s, a1d, b1, tid);
    gat_layer<64, 64, 4>(s, W2, a2s, a2d, b2, tid);
    gat_layer<64, 64, 4>(s, W3, a3s, a3d, b3, tid);
    gat_layer<64, 64, 1>(s, W4, a4s, a4d, b4, tid);
    __syncthreads();

    // ---------------- Mean pool + FC + softmax ----------------
    if (tid < 64) {
        float acc = 0.f;
#pragma unroll
        for (int i = 0; i < 32; i++) acc += s.X[i * XSTR + tid];
        s.Ht[tid] = acc * (1.f / 32.f);
    }
    __syncthreads();
    if (tid < 2) {
        float acc = fcb[tid];
#pragma unroll
        for (int k2 = 0; k2 < 64; k2++) acc += s.Ht[k2] * fcW[k2 * 2 + tid];
        s.ED[tid] = acc;
    }
    __syncthreads();
    if (tid == 0) {
        float l0 = s.ED[0], l1 = s.ED[1];
        out[g * 2 + 0] = l0;
        out[g * 2 + 1] = l1;
        float mx = fmaxf(l0, l1);
        float e0 = __expf(l0 - mx), e1 = __expf(l1 - mx);
        float inv = 1.f / (e0 + e1);
        out[out_half + g * 2 + 0] = e0 * inv;
        out[out_half + g * 2 + 1] = e1 * inv;
    }
}

extern "C" void kernel_launch(void* const* d_in, const int* in_sizes, int n_in,
                              void* d_out, int out_size)
{
    const float* x   = (const float*)d_in[0];
    const int*   ei  = (const int*)d_in[1];
    const float* Wq  = (const float*)d_in[3];
    const float* Wk  = (const float*)d_in[4];
    const float* Wv  = (const float*)d_in[5];
    const float* W1  = (const float*)d_in[6];
    const float* a1s = (const float*)d_in[7];
    const float* a1d = (const float*)d_in[8];
    const float* b1  = (const float*)d_in[9];
    const float* W2  = (const float*)d_in[10];
    const float* a2s = (const float*)d_in[11];
    const float* a2d = (const float*)d_in[12];
    const float* b2  = (const float*)d_in[13];
    const float* W3  = (const float*)d_in[14];
    const float* a3s = (const float*)d_in[15];
    const float* a3d = (const float*)d_in[16];
    const float* b3  = (const float*)d_in[17];
    const float* W4  = (const float*)d_in[18];
    const float* a4s = (const float*)d_in[19];
    const float* a4d = (const float*)d_in[20];
    const float* b4  = (const float*)d_in[21];
    const float* fcW = (const float*)d_in[22];
    const float* fcb = (const float*)d_in[23];

    gnn_kernel<<<NGRAPH, 256>>>(x, ei, Wq, Wk, Wv,
                                W1, a1s, a1d, b1,
                                W2, a2s, a2d, b2,
                                W3, a3s, a3d, b3,
                                W4, a4s, a4d, b4,
                                fcW, fcb,
                                (float*)d_out, out_size / 2);
}

// round 10
// speedup vs baseline: 1.6040x; 1.0627x over previous
#include <cuda_runtime.h>
#include <cstdint>

#define NODES 32
#define NGRAPH 4096
#define FEAT 10
#define EPG 256
#define EDGES_TOTAL (NGRAPH * EPG)

#define XSTR 68     // X row stride
#define WTSTR 68    // Wt row stride (GAT weights, transposed)
#define HTSTR 40    // GAT Ht row stride (conflict-free for a/g lane map)
#define QSTR 36     // attention Q/K/V row stride
#define ASTR 36     // alpha row stride
#define AHD 1152    // alpha head stride (32*36)
#define CSTR 36     // multiplicity row stride (float4-aligned)

typedef unsigned long long ull;

struct Smem {
    float WA[4608];   // Wt[k][m] 64x68 -> alpha[hd][i][36]; attn: Wq/Wk/Wv^T (stride QSTR)
    float Ht[2560];   // GAT h^T [k][i] 64x40; attn: Q/K/V [s][c] stride 36; pool scratch
    float X[2176];    // activations [i][m] 32x68
    float C[1152];    // multiplicity [i][j] 32x36
    float ES[128];
    float ED[128];
    float AS[64], AD[64], B[64];
};

__device__ __forceinline__ void fma2(ull& acc, ull a, ull b) {
    asm("fma.rn.f32x2 %0, %1, %2, %0;" : "+l"(acc) : "l"(a), "l"(b));
}
__device__ __forceinline__ float red2(ull v) {
    float lo, hi;
    asm("mov.b64 {%0,%1}, %2;" : "=f"(lo), "=f"(hi) : "l"(v));
    return lo + hi;
}
__device__ __forceinline__ ulonglong2 ld2(const float* p) {
    return *(const ulonglong2*)p;
}
__device__ __forceinline__ float lrelu(float v, float s) { return v > 0.f ? v : v * s; }

template<int CIN, int CINP, int H>
__device__ void gat_layer(Smem& s,
                          const float* __restrict__ W, const float* __restrict__ as_,
                          const float* __restrict__ ad_, const float* __restrict__ b_,
                          int tid)
{
    __syncthreads();   // prior X writes / alpha reads complete

    // ---- Stage Wt[k][m] conflict-free: lanes k-low(8) x m-low(4) -> banks 4k+m distinct
    {
        const int kk = (tid & 7) + 8 * (tid >> 5);     // 0..31
        const int m0 = (tid >> 3) & 3;
#pragma unroll
        for (int kh = 0; kh < 64; kh += 32) {
#pragma unroll
            for (int p = 0; p < CINP / 4; p++) {
                int m = m0 + 4 * p;
                s.WA[(kk + kh) * WTSTR + m] = (m < CIN) ? W[m * 64 + kk + kh] : 0.f;
            }
        }
    }
    if (tid < 64) { s.AS[tid] = as_[tid]; s.AD[tid] = ad_[tid]; s.B[tid] = b_[tid]; }
    __syncthreads();

    const int a  = tid & 3;          // k-low
    const int g2 = (tid >> 2) & 7;   // row-low
    const int w  = tid >> 5;         // warp 0..3

    // ---- mm1: Ht[k][i] = sum_m X[i][m] * Wt[k][m]   (4x4 tiles)
    {
        ull acc[4][4] = {};
#pragma unroll
        for (int mg = 0; mg < CINP; mg += 4) {
            ulonglong2 wv[4];
#pragma unroll
            for (int q = 0; q < 4; q++)
                wv[q] = ld2(&s.WA[(16 * w + a + 4 * q) * WTSTR + mg]);
#pragma unroll
            for (int r = 0; r < 4; r++) {
                ulonglong2 xv = ld2(&s.X[(g2 + 8 * r) * XSTR + mg]);
#pragma unroll
                for (int q = 0; q < 4; q++) {
                    fma2(acc[r][q], xv.x, wv[q].x);
                    fma2(acc[r][q], xv.y, wv[q].y);
                }
            }
        }
#pragma unroll
        for (int r = 0; r < 4; r++)
#pragma unroll
            for (int q = 0; q < 4; q++)
                s.Ht[(16 * w + a + 4 * q) * HTSTR + g2 + 8 * r] = red2(acc[r][q]);
    }
    __syncthreads();

    // ---- e_s[j], e_d[j] per head (partials for H=1)
    {
        const int j = tid & 31, seg = tid >> 5;
        const int c0 = seg * 16;
        float as0 = 0.f, ad0 = 0.f;
#pragma unroll
        for (int c = 0; c < 16; c++) {
            float hv = s.Ht[(c0 + c) * HTSTR + j];
            as0 += hv * s.AS[c0 + c];
            ad0 += hv * s.AD[c0 + c];
        }
        s.ES[seg * 32 + j] = as0;
        s.ED[seg * 32 + j] = ad0;
    }
    __syncthreads();
    if (H == 1) {
        if (tid < 32) {
            s.ES[tid] = s.ES[tid] + s.ES[32 + tid] + s.ES[64 + tid] + s.ES[96 + tid];
            s.ED[tid] = s.ED[tid] + s.ED[32 + tid] + s.ED[64 + tid] + s.ED[96 + tid];
        }
        __syncthreads();
    }

    // ---- masked, multiplicity-weighted softmax; alpha -> WA (Wt dead)
    if (tid < 32 * H) {
        const int i = tid & 31, hd = tid >> 5;
        const float edi = s.ED[hd * 32 + i];
        const float* esr = &s.ES[hd * 32];
        const float* crow = &s.C[i * CSTR];
        float ev[32], cw[32];
        float mx = -1e30f;
#pragma unroll
        for (int jg = 0; jg < 32; jg += 4) {
            float4 e4 = *(const float4*)&esr[jg];
            float4 c4 = *(const float4*)&crow[jg];
            float es[4] = {e4.x, e4.y, e4.z, e4.w};
            float cs[4] = {c4.x, c4.y, c4.z, c4.w};
#pragma unroll
            for (int u = 0; u < 4; u++) {
                float e = lrelu(es[u] + edi, 0.2f);
                ev[jg + u] = e; cw[jg + u] = cs[u];
                if (cs[u] > 0.f && e > mx) mx = e;
            }
        }
        float den = 0.f;
#pragma unroll
        for (int j = 0; j < 32; j++) {
            float wv = cw[j] * __expf(ev[j] - mx);
            ev[j] = wv; den += wv;
        }
        float inv = 1.f / (den + 1e-16f);
        float* arow = &s.WA[hd * AHD + i * ASTR];
#pragma unroll
        for (int jg = 0; jg < 32; jg += 4)
            *(float4*)&arow[jg] = make_float4(ev[jg] * inv, ev[jg + 1] * inv,
                                              ev[jg + 2] * inv, ev[jg + 3] * inv);
    }
    __syncthreads();

    // ---- mm2: X[i][k] = lrelu( sum_j alpha[hd][i][j]*Ht[k][j] + b[k] )  (4x4 tiles)
    {
        const int hd = (H == 4) ? w : 0;
        ull acc[4][4] = {};
#pragma unroll
        for (int jg = 0; jg < 32; jg += 4) {
            ulonglong2 hv[4];
#pragma unroll
            for (int q = 0; q < 4; q++)
                hv[q] = ld2(&s.Ht[(16 * w + a + 4 * q) * HTSTR + jg]);
#pragma unroll
            for (int r = 0; r < 4; r++) {
                ulonglong2 av = ld2(&s.WA[hd * AHD + (g2 + 8 * r) * ASTR + jg]);
#pragma unroll
                for (int q = 0; q < 4; q++) {
                    fma2(acc[r][q], av.x, hv[q].x);
                    fma2(acc[r][q], av.y, hv[q].y);
                }
            }
        }
#pragma unroll
        for (int r = 0; r < 4; r++)
#pragma unroll
            for (int q = 0; q < 4; q++) {
                int k = 16 * w + a + 4 * q;
                s.X[(g2 + 8 * r) * XSTR + k] = lrelu(red2(acc[r][q]) + s.B[k], 0.01f);
            }
    }
}

__global__ __launch_bounds__(128, 5) void gnn_kernel(
    const float* __restrict__ x, const int* __restrict__ ei,
    const float* __restrict__ Wq, const float* __restrict__ Wk, const float* __restrict__ Wv,
    const float* __restrict__ W1, const float* __restrict__ a1s, const float* __restrict__ a1d, const float* __restrict__ b1,
    const float* __restrict__ W2, const float* __restrict__ a2s, const float* __restrict__ a2d, const float* __restrict__ b2,
    const float* __restrict__ W3, const float* __restrict__ a3s, const float* __restrict__ a3d, const float* __restrict__ b3,
    const float* __restrict__ W4, const float* __restrict__ a4s, const float* __restrict__ a4d, const float* __restrict__ b4,
    const float* __restrict__ fcW, const float* __restrict__ fcb,
    float* __restrict__ out, int out_half)
{
    __shared__ Smem s;
    const int tid = threadIdx.x;
    const int g = blockIdx.x;

    const bool is64 = (ei[2 * (size_t)EDGES_TOTAL - 1] == 0);

    // ---------------- Attention layer ----------------
    // P1: Wq/Wk/Wv transposed into WA [c][i] stride QSTR; lanes i-low(4) x c-low(8)
    {
        const int il = tid & 3;
        const int cl = (tid >> 2) & 7;
        const int ih = tid >> 5;          // 0..3
#pragma unroll
        for (int e = 0; e < 24; e++) {
            int which = e >> 3, f = e & 7;
            int i = il + 4 * ih + 16 * (f & 1);
            int c = cl + 8 * ((f >> 1) & 1) + 16 * (f >> 2);
            const float* Wsrc = (which == 0) ? Wq : (which == 1) ? Wk : Wv;
            s.WA[which * 1280 + c * QSTR + i] = Wsrc[i * 32 + c];
        }
    }
    for (int t = tid; t < 320; t += 128) {
        int si = t >> 5, ii = t & 31;
        s.C[si * 32 + ii] = x[(size_t)(g * 32 + ii) * FEAT + si];
    }
    __syncthreads();

    // P2: Q,K,V [s][c] stride 36 -> Ht at 0/360/720
    for (int o = tid; o < 960; o += 128) {
        int which = o / 320, r = o - which * 320;
        int si = r >> 5, c = r & 31;
        const float* wt = &s.WA[which * 1280 + c * QSTR];
        const float* at = &s.C[si * 32];
        ull acc = 0;
#pragma unroll
        for (int ig = 0; ig < 32; ig += 4) {
            ulonglong2 a2 = ld2(at + ig), w2 = ld2(wt + ig);
            fma2(acc, a2.x, w2.x); fma2(acc, a2.y, w2.y);
        }
        s.Ht[which * 360 + si * 36 + c] = red2(acc);
    }
    __syncthreads();

    // P3: scores [s][t] -> ES; zero C
    for (int t = tid; t < NODES * CSTR; t += 128) s.C[t] = 0.f;
    if (tid < 100) {
        int si = tid / 10, ti = tid - si * 10;
        ull acc = 0;
#pragma unroll
        for (int cg = 0; cg < 32; cg += 4) {
            ulonglong2 q2 = ld2(&s.Ht[si * 36 + cg]);
            ulonglong2 k2 = ld2(&s.Ht[360 + ti * 36 + cg]);
            fma2(acc, q2.x, k2.x); fma2(acc, q2.y, k2.y);
        }
        s.ES[si * 10 + ti] = red2(acc);
    }
    __syncthreads();

    // P4: multiplicity matrix + attention row softmax
#pragma unroll
    for (int half = 0; half < 2; half++) {
        size_t eg = (size_t)g * EPG + tid + 128 * half;
        int srcv, dstv;
        if (is64) {
            srcv = ei[2 * eg];
            dstv = ei[2 * ((size_t)EDGES_TOTAL + eg)];
        } else {
            srcv = ei[eg];
            dstv = ei[(size_t)EDGES_TOTAL + eg];
        }
        int sl = srcv - g * 32, dl = dstv - g * 32;
        atomicAdd(&s.C[dl * CSTR + sl], 1.0f);
    }
    if (tid < 32) atomicAdd(&s.C[tid * CSTR + tid], 1.0f);  // self-loops
    if (tid < 10) {
        float mx = -1e30f;
#pragma unroll
        for (int t2 = 0; t2 < 10; t2++) mx = fmaxf(mx, s.ES[tid * 10 + t2]);
        float e[10], sum = 0.f;
#pragma unroll
        for (int t2 = 0; t2 < 10; t2++) { e[t2] = __expf(s.ES[tid * 10 + t2] - mx); sum += e[t2]; }
        float inv = 1.f / sum;
#pragma unroll
        for (int t2 = 0; t2 < 10; t2++) s.ES[tid * 10 + t2] = e[t2] * inv;
    }
    __syncthreads();

    // P5: att out[s][i] -> X[i][s]; zero pad cols 10,11
    for (int t = tid; t < 320; t += 128) {
        int si = t >> 5, ii = t & 31;
        float acc = 0.f;
#pragma unroll
        for (int t2 = 0; t2 < 10; t2++)
            acc += s.ES[si * 10 + t2] * s.Ht[720 + t2 * 36 + ii];
        s.X[ii * XSTR + si] = acc;
    }
    if (tid < 64) s.X[(tid & 31) * XSTR + 10 + (tid >> 5)] = 0.f;

    // ---------------- GAT stack ----------------
    gat_layer<10, 12, 4>(s, W1, a1s, a1d, b1, tid);
    gat_layer<64, 64, 4>(s, W2, a2s, a2d, b2, tid);
    gat_layer<64, 64, 4>(s, W3, a3s, a3d, b3, tid);
    gat_layer<64, 64, 1>(s, W4, a4s, a4d, b4, tid);
    __syncthreads();

    // ---------------- Mean pool + FC + softmax ----------------
    if (tid < 64) {
        float acc = 0.f;
#pragma unroll
        for (int i = 0; i < 32; i++) acc += s.X[i * XSTR + tid];
        s.Ht[tid] = acc * (1.f / 32.f);
    }
    __syncthreads();
    if (tid < 2) {
        float acc = fcb[tid];
#pragma unroll
        for (int k2 = 0; k2 < 64; k2++) acc += s.Ht[k2] * fcW[k2 * 2 + tid];
        s.ED[tid] = acc;
    }
    __syncthreads();
    if (tid == 0) {
        float l0 = s.ED[0], l1 = s.ED[1];
        out[g * 2 + 0] = l0;
        out[g * 2 + 1] = l1;
        float mx = fmaxf(l0, l1);
        float e0 = __expf(l0 - mx), e1 = __expf(l1 - mx);
        float inv = 1.f / (e0 + e1);
        out[out_half + g * 2 + 0] = e0 * inv;
        out[out_half + g * 2 + 1] = e1 * inv;
    }
}

extern "C" void kernel_launch(void* const* d_in, const int* in_sizes, int n_in,
                              void* d_out, int out_size)
{
    const float* x   = (const float*)d_in[0];
    const int*   ei  = (const int*)d_in[1];
    const float* Wq  = (const float*)d_in[3];
    const float* Wk  = (const float*)d_in[4];
    const float* Wv  = (const float*)d_in[5];
    const float* W1  = (const float*)d_in[6];
    const float* a1s = (const float*)d_in[7];
    const float* a1d = (const float*)d_in[8];
    const float* b1  = (const float*)d_in[9];
    const float* W2  = (const float*)d_in[10];
    const float* a2s = (const float*)d_in[11];
    const float* a2d = (const float*)d_in[12];
    const float* b2  = (const float*)d_in[13];
    const float* W3  = (const float*)d_in[14];
    const float* a3s = (const float*)d_in[15];
    const float* a3d = (const float*)d_in[16];
    const float* b3  = (const float*)d_in[17];
    const float* W4  = (const float*)d_in[18];
    const float* a4s = (const float*)d_in[19];
    const float* a4d = (const float*)d_in[20];
    const float* b4  = (const float*)d_in[21];
    const float* fcW = (const float*)d_in[22];
    const float* fcb = (const float*)d_in[23];

    gnn_kernel<<<NGRAPH, 128>>>(x, ei, Wq, Wk, Wv,
                                W1, a1s, a1d, b1,
                                W2, a2s, a2d, b2,
                                W3, a3s, a3d, b3,
                                W4, a4s, a4d, b4,
                                fcW, fcb,
                                (float*)d_out, out_size / 2);
}

// round 11
// speedup vs baseline: 1.7591x; 1.0967x over previous
#include <cuda_runtime.h>
#include <cstdint>

#define NODES 32
#define NGRAPH 4096
#define FEAT 10
#define EPG 256
#define EDGES_TOTAL (NGRAPH * EPG)

#define XSTR 68     // X row stride [i][k]
#define WSTR 68     // weight rows [m][k]
#define HSTR 68     // H rows [j][k]
#define QSTR 36     // attention Q/K/V row stride
#define ASTR 36     // alpha (transposed [j][i]) row stride
#define AHD  1152   // alpha head stride (32*36)
#define CSTR 33     // multiplicity row stride (scalar conflict-free)

typedef unsigned long long ull;

struct Smem {
    float WA[4608];   // weights [m][WSTR] -> alphaT [hd][j][i]; attn Wq/Wk/Wv^T
    float H[2176];    // GAT h [j][68]; attn Q/K/V stride 36; pool scratch
    float X[2176];    // activations [i][68]
    float C[1056];    // multiplicity [i][33]
    float ES[128], ED[128];
    float AS[64], AD[64], B[64];
};

// ---------- f32x2 helpers (attention phase) ----------
__device__ __forceinline__ void fma2(ull& acc, ull a, ull b) {
    asm("fma.rn.f32x2 %0, %1, %2, %0;" : "+l"(acc) : "l"(a), "l"(b));
}
__device__ __forceinline__ float red2(ull v) {
    float lo, hi;
    asm("mov.b64 {%0,%1}, %2;" : "=f"(lo), "=f"(hi) : "l"(v));
    return lo + hi;
}
__device__ __forceinline__ ulonglong2 ld2(const float* p) { return *(const ulonglong2*)p; }
__device__ __forceinline__ float lrelu(float v, float s) { return v > 0.f ? v : v * s; }

// ---------- tf32 3x MMA helpers ----------
__device__ __forceinline__ uint32_t cvt_tf32(float f) {
    uint32_t u; asm("cvt.rna.tf32.f32 %0, %1;" : "=r"(u) : "f"(f)); return u;
}
struct TF2 { uint32_t hi, lo; };
__device__ __forceinline__ TF2 tf32x(float f) {
    TF2 r; r.hi = cvt_tf32(f);
    r.lo = cvt_tf32(f - __uint_as_float(r.hi));
    return r;
}
__device__ __forceinline__ void mma8(float* d, const uint32_t* a, const uint32_t* b) {
    asm("mma.sync.aligned.m16n8k8.row.col.f32.tf32.tf32.f32 "
        "{%0,%1,%2,%3}, {%4,%5,%6,%7}, {%8,%9}, {%0,%1,%2,%3};"
        : "+f"(d[0]), "+f"(d[1]), "+f"(d[2]), "+f"(d[3])
        : "r"(a[0]), "r"(a[1]), "r"(a[2]), "r"(a[3]), "r"(b[0]), "r"(b[1]));
}
__device__ __forceinline__ void mma3x(float* d, const TF2* a, const TF2* b) {
    uint32_t ah[4] = {a[0].hi, a[1].hi, a[2].hi, a[3].hi};
    uint32_t al[4] = {a[0].lo, a[1].lo, a[2].lo, a[3].lo};
    uint32_t bh[2] = {b[0].hi, b[1].hi};
    uint32_t bl[2] = {b[0].lo, b[1].lo};
    mma8(d, al, bh);
    mma8(d, ah, bl);
    mma8(d, ah, bh);
}

template<int CIN, int CINP, int H4>
__device__ void gat_layer(Smem& s,
                          const float* __restrict__ W, const float* __restrict__ as_,
                          const float* __restrict__ ad_, const float* __restrict__ b_,
                          int tid)
{
    const int lane = tid & 31;
    const int w    = tid >> 5;     // warp 0..3, owns cols 16w..16w+15 (= head w for H4=4)
    const int g    = lane >> 2;    // 0..7
    const int t4   = lane & 3;     // 0..3

    __syncthreads();   // prior X writes / prior alphaT (in WA) reads complete

    // ---- stage W [m][k] natural layout, zero-pad rows to CINP ----
    for (int idx = tid; idx < CINP * 16; idx += 128) {
        int m = idx >> 4, c4 = (idx & 15) * 4;
        float4 v = (m < CIN) ? *(const float4*)&W[m * 64 + c4]
                             : make_float4(0.f, 0.f, 0.f, 0.f);
        *(float4*)&s.WA[m * WSTR + c4] = v;
    }
    if (tid < 64) { s.AS[tid] = as_[tid]; s.AD[tid] = ad_[tid]; s.B[tid] = b_[tid]; }
    __syncthreads();

    // ---- mm1: H = X @ W  (warp w -> 16 cols), 3xTF32 ----
    float d[2][2][4] = {};
#pragma unroll
    for (int st = 0; st < CINP / 8; st++) {
        const int m0 = 8 * st;
        TF2 a[2][4], b[2][2];
#pragma unroll
        for (int ti = 0; ti < 2; ti++) {
            int r0 = 16 * ti + g;
            a[ti][0] = tf32x(s.X[r0 * XSTR + m0 + t4]);
            a[ti][1] = tf32x(s.X[(r0 + 8) * XSTR + m0 + t4]);
            a[ti][2] = tf32x(s.X[r0 * XSTR + m0 + t4 + 4]);
            a[ti][3] = tf32x(s.X[(r0 + 8) * XSTR + m0 + t4 + 4]);
        }
#pragma unroll
        for (int nt = 0; nt < 2; nt++) {
            int col = 16 * w + 8 * nt + g;
            b[nt][0] = tf32x(s.WA[(m0 + t4) * WSTR + col]);
            b[nt][1] = tf32x(s.WA[(m0 + t4 + 4) * WSTR + col]);
        }
#pragma unroll
        for (int ti = 0; ti < 2; ti++)
#pragma unroll
            for (int nt = 0; nt < 2; nt++)
                mma3x(d[ti][nt], a[ti], b[nt]);
    }

    // ---- e_s/e_d partials straight from D-fragments ----
    {
        float esp[4] = {0.f, 0.f, 0.f, 0.f}, edp[4] = {0.f, 0.f, 0.f, 0.f};
#pragma unroll
        for (int ti = 0; ti < 2; ti++)
#pragma unroll
            for (int nt = 0; nt < 2; nt++) {
                int cb = 16 * w + 8 * nt + 2 * t4;
                float s0 = s.AS[cb], s1 = s.AS[cb + 1];
                float a0 = s.AD[cb], a1 = s.AD[cb + 1];
                esp[2 * ti]     += d[ti][nt][0] * s0 + d[ti][nt][1] * s1;
                esp[2 * ti + 1] += d[ti][nt][2] * s0 + d[ti][nt][3] * s1;
                edp[2 * ti]     += d[ti][nt][0] * a0 + d[ti][nt][1] * a1;
                edp[2 * ti + 1] += d[ti][nt][2] * a0 + d[ti][nt][3] * a1;
            }
#pragma unroll
        for (int m = 1; m <= 2; m <<= 1)
#pragma unroll
            for (int r = 0; r < 4; r++) {
                esp[r] += __shfl_xor_sync(0xFFFFFFFF, esp[r], m);
                edp[r] += __shfl_xor_sync(0xFFFFFFFF, edp[r], m);
            }
        if (t4 == 0) {
#pragma unroll
            for (int r = 0; r < 4; r++) {
                int row = 16 * (r >> 1) + 8 * (r & 1) + g;
                s.ES[w * 32 + row] = esp[r];
                s.ED[w * 32 + row] = edp[r];
            }
        }
    }

    // ---- store H fragments [j][k] ----
#pragma unroll
    for (int ti = 0; ti < 2; ti++)
#pragma unroll
        for (int nt = 0; nt < 2; nt++) {
            int r0 = 16 * ti + g, col = 16 * w + 8 * nt + 2 * t4;
            *(float2*)&s.H[r0 * HSTR + col]       = make_float2(d[ti][nt][0], d[ti][nt][1]);
            *(float2*)&s.H[(r0 + 8) * HSTR + col] = make_float2(d[ti][nt][2], d[ti][nt][3]);
        }

    if (H4 == 1) {
        __syncthreads();
        if (tid < 32) {
            s.ES[tid] = s.ES[tid] + s.ES[32 + tid] + s.ES[64 + tid] + s.ES[96 + tid];
            s.ED[tid] = s.ED[tid] + s.ED[32 + tid] + s.ED[64 + tid] + s.ED[96 + tid];
        }
        __syncthreads();
    } else {
        __syncwarp();
    }

    // ---- masked multiplicity-weighted softmax; alphaT[j][i] -> WA ----
    if (tid < 32 * H4) {
        const int i = tid & 31, hd = tid >> 5;
        const float edi = s.ED[hd * 32 + i];
        const float* esr = &s.ES[hd * 32];
        const float* crow = &s.C[i * CSTR];
        float ev[32];
        float mx = -1e30f;
#pragma unroll
        for (int j = 0; j < 32; j++) {
            float e = lrelu(esr[j] + edi, 0.2f);
            ev[j] = e;
            if (crow[j] > 0.f && e > mx) mx = e;
        }
        float den = 0.f;
#pragma unroll
        for (int j = 0; j < 32; j++) {
            float wv = crow[j] * __expf(ev[j] - mx);
            ev[j] = wv; den += wv;
        }
        float inv = 1.f / (den + 1e-16f);
        float* at0 = &s.WA[hd * AHD];
#pragma unroll
        for (int j = 0; j < 32; j++)
            at0[j * ASTR + i] = ev[j] * inv;     // transposed, conflict-free
    }
    if (H4 == 1) __syncthreads(); else __syncwarp();

    // ---- mm2: X[i][col] = lrelu( alpha_hd @ H + b ), 3xTF32 ----
    {
        const int hd = (H4 == 4) ? w : 0;
        const float* AT = &s.WA[hd * AHD];
        float d2[2][2][4] = {};
#pragma unroll
        for (int st = 0; st < 4; st++) {
            const int j0 = 8 * st;
            TF2 a[2][4], b[2][2];
#pragma unroll
            for (int ti = 0; ti < 2; ti++) {
                int r0 = 16 * ti + g;
                a[ti][0] = tf32x(AT[(j0 + t4) * ASTR + r0]);
                a[ti][1] = tf32x(AT[(j0 + t4) * ASTR + r0 + 8]);
                a[ti][2] = tf32x(AT[(j0 + t4 + 4) * ASTR + r0]);
                a[ti][3] = tf32x(AT[(j0 + t4 + 4) * ASTR + r0 + 8]);
            }
#pragma unroll
            for (int nt = 0; nt < 2; nt++) {
                int col = 16 * w + 8 * nt + g;
                b[nt][0] = tf32x(s.H[(j0 + t4) * HSTR + col]);
                b[nt][1] = tf32x(s.H[(j0 + t4 + 4) * HSTR + col]);
            }
#pragma unroll
            for (int ti = 0; ti < 2; ti++)
#pragma unroll
                for (int nt = 0; nt < 2; nt++)
                    mma3x(d2[ti][nt], a[ti], b[nt]);
        }
#pragma unroll
        for (int ti = 0; ti < 2; ti++)
#pragma unroll
            for (int nt = 0; nt < 2; nt++) {
                int r0 = 16 * ti + g, col = 16 * w + 8 * nt + 2 * t4;
                float b0 = s.B[col], b1 = s.B[col + 1];
                *(float2*)&s.X[r0 * XSTR + col] =
                    make_float2(lrelu(d2[ti][nt][0] + b0, 0.01f), lrelu(d2[ti][nt][1] + b1, 0.01f));
                *(float2*)&s.X[(r0 + 8) * XSTR + col] =
                    make_float2(lrelu(d2[ti][nt][2] + b0, 0.01f), lrelu(d2[ti][nt][3] + b1, 0.01f));
            }
    }
}

__global__ __launch_bounds__(128, 5) void gnn_kernel(
    const float* __restrict__ x, const int* __restrict__ ei,
    const float* __restrict__ Wq, const float* __restrict__ Wk, const float* __restrict__ Wv,
    const float* __restrict__ W1, const float* __restrict__ a1s, const float* __restrict__ a1d, const float* __restrict__ b1,
    const float* __restrict__ W2, const float* __restrict__ a2s, const float* __restrict__ a2d, const float* __restrict__ b2,
    const float* __restrict__ W3, const float* __restrict__ a3s, const float* __restrict__ a3d, const float* __restrict__ b3,
    const float* __restrict__ W4, const float* __restrict__ a4s, const float* __restrict__ a4d, const float* __restrict__ b4,
    const float* __restrict__ fcW, const float* __restrict__ fcb,
    float* __restrict__ out, int out_half)
{
    __shared__ Smem s;
    const int tid = threadIdx.x;
    const int g = blockIdx.x;

    const bool is64 = (ei[2 * (size_t)EDGES_TOTAL - 1] == 0);

    // ---------------- Attention layer (f32 FFMA2 path) ----------------
    // P1: Wq/Wk/Wv transposed into WA [c][i] stride QSTR; lanes i-low(4) x c-low(8)
    {
        const int il = tid & 3;
        const int cl = (tid >> 2) & 7;
        const int ih = tid >> 5;
#pragma unroll
        for (int e = 0; e < 24; e++) {
            int which = e >> 3, f = e & 7;
            int i = il + 4 * ih + 16 * (f & 1);
            int c = cl + 8 * ((f >> 1) & 1) + 16 * (f >> 2);
            const float* Wsrc = (which == 0) ? Wq : (which == 1) ? Wk : Wv;
            s.WA[which * 1280 + c * QSTR + i] = Wsrc[i * 32 + c];
        }
    }
    for (int t = tid; t < 320; t += 128) {
        int si = t >> 5, ii = t & 31;
        s.C[si * 32 + ii] = x[(size_t)(g * 32 + ii) * FEAT + si];
    }
    __syncthreads();

    // P2: Q,K,V [s][c] stride 36 -> H at 0/360/720
    for (int o = tid; o < 960; o += 128) {
        int which = o / 320, r = o - which * 320;
        int si = r >> 5, c = r & 31;
        const float* wt = &s.WA[which * 1280 + c * QSTR];
        const float* at = &s.C[si * 32];
        ull acc = 0;
#pragma unroll
        for (int ig = 0; ig < 32; ig += 4) {
            ulonglong2 a2 = ld2(at + ig), w2 = ld2(wt + ig);
            fma2(acc, a2.x, w2.x); fma2(acc, a2.y, w2.y);
        }
        s.H[which * 360 + si * 36 + c] = red2(acc);
    }
    __syncthreads();

    // P3: scores [s][t] -> ES; zero C
    for (int t = tid; t < NODES * CSTR; t += 128) s.C[t] = 0.f;
    if (tid < 100) {
        int si = tid / 10, ti = tid - si * 10;
        ull acc = 0;
#pragma unroll
        for (int cg = 0; cg < 32; cg += 4) {
            ulonglong2 q2 = ld2(&s.H[si * 36 + cg]);
            ulonglong2 k2 = ld2(&s.H[360 + ti * 36 + cg]);
            fma2(acc, q2.x, k2.x); fma2(acc, q2.y, k2.y);
        }
        s.ES[si * 10 + ti] = red2(acc);
    }
    __syncthreads();

    // P4: multiplicity matrix + attention row softmax
#pragma unroll
    for (int half = 0; half < 2; half++) {
        size_t eg = (size_t)g * EPG + tid + 128 * half;
        int srcv, dstv;
        if (is64) {
            srcv = ei[2 * eg];
            dstv = ei[2 * ((size_t)EDGES_TOTAL + eg)];
        } else {
            srcv = ei[eg];
            dstv = ei[(size_t)EDGES_TOTAL + eg];
        }
        int sl = srcv - g * 32, dl = dstv - g * 32;
        atomicAdd(&s.C[dl * CSTR + sl], 1.0f);
    }
    if (tid < 32) atomicAdd(&s.C[tid * CSTR + tid], 1.0f);  // self-loops
    if (tid < 10) {
        float mx = -1e30f;
#pragma unroll
        for (int t2 = 0; t2 < 10; t2++) mx = fmaxf(mx, s.ES[tid * 10 + t2]);
        float e[10], sum = 0.f;
#pragma unroll
        for (int t2 = 0; t2 < 10; t2++) { e[t2] = __expf(s.ES[tid * 10 + t2] - mx); sum += e[t2]; }
        float inv = 1.f / sum;
#pragma unroll
        for (int t2 = 0; t2 < 10; t2++) s.ES[tid * 10 + t2] = e[t2] * inv;
    }
    __syncthreads();

    // P5: att out[s][i] -> X[i][s]; zero pad cols 10..15
    for (int t = tid; t < 320; t += 128) {
        int si = t >> 5, ii = t & 31;
        float acc = 0.f;
#pragma unroll
        for (int t2 = 0; t2 < 10; t2++)
            acc += s.ES[si * 10 + t2] * s.H[720 + t2 * 36 + ii];
        s.X[ii * XSTR + si] = acc;
    }
    for (int t = tid; t < 192; t += 128) {
        int ii = t & 31, cc = 10 + (t >> 5);
        s.X[ii * XSTR + cc] = 0.f;
    }

    // ---------------- GAT stack (tensor-core 3xTF32) ----------------
    gat_layer<10, 16, 4>(s, W1, a1s, a1d, b1, tid);
    gat_layer<64, 64, 4>(s, W2, a2s, a2d, b2, tid);
    gat_layer<64, 64, 4>(s, W3, a3s, a3d, b3, tid);
    gat_layer<64, 64, 1>(s, W4, a4s, a4d, b4, tid);
    __syncthreads();

    // ---------------- Mean pool + FC + softmax ----------------
    if (tid < 64) {
        float acc = 0.f;
#pragma unroll
        for (int i = 0; i < 32; i++) acc += s.X[i * XSTR + tid];
        s.H[tid] = acc * (1.f / 32.f);
    }
    __syncthreads();
    if (tid < 2) {
        float acc = fcb[tid];
#pragma unroll
        for (int k2 = 0; k2 < 64; k2++) acc += s.H[k2] * fcW[k2 * 2 + tid];
        s.ED[tid] = acc;
    }
    __syncthreads();
    if (tid == 0) {
        float l0 = s.ED[0], l1 = s.ED[1];
        out[g * 2 + 0] = l0;
        out[g * 2 + 1] = l1;
        float mx = fmaxf(l0, l1);
        float e0 = __expf(l0 - mx), e1 = __expf(l1 - mx);
        float inv = 1.f / (e0 + e1);
        out[out_half + g * 2 + 0] = e0 * inv;
        out[out_half + g * 2 + 1] = e1 * inv;
    }
}

extern "C" void kernel_launch(void* const* d_in, const int* in_sizes, int n_in,
                              void* d_out, int out_size)
{
    const float* x   = (const float*)d_in[0];
    const int*   ei  = (const int*)d_in[1];
    const float* Wq  = (const float*)d_in[3];
    const float* Wk  = (const float*)d_in[4];
    const float* Wv  = (const float*)d_in[5];
    const float* W1  = (const float*)d_in[6];
    const float* a1s = (const float*)d_in[7];
    const float* a1d = (const float*)d_in[8];
    const float* b1  = (const float*)d_in[9];
    const float* W2  = (const float*)d_in[10];
    const float* a2s = (const float*)d_in[11];
    const float* a2d = (const float*)d_in[12];
    const float* b2  = (const float*)d_in[13];
    const float* W3  = (const float*)d_in[14];
    const float* a3s = (const float*)d_in[15];
    const float* a3d = (const float*)d_in[16];
    const float* b3  = (const float*)d_in[17];
    const float* W4  = (const float*)d_in[18];
    const float* a4s = (const float*)d_in[19];
    const float* a4d = (const float*)d_in[20];
    const float* b4  = (const float*)d_in[21];
    const float* fcW = (const float*)d_in[22];
    const float* fcb = (const float*)d_in[23];

    gnn_kernel<<<NGRAPH, 128>>>(x, ei, Wq, Wk, Wv,
                                W1, a1s, a1d, b1,
                                W2, a2s, a2d, b2,
                                W3, a3s, a3d, b3,
                                W4, a4s, a4d, b4,
                                fcW, fcb,
                                (float*)d_out, out_size / 2);
}

// round 15
// speedup vs baseline: 1.9008x; 1.0806x over previous
#include <cuda_runtime.h>
#include <cstdint>

#define NODES 32
#define NGRAPH 4096
#define FEAT 10
#define EPG 256
#define EDGES_TOTAL (NGRAPH * EPG)

#define XSTR 68     // X row stride [i][k]
#define WSTR 68     // weight rows [m][k]
#define HSTR 68     // H rows [j][k]
#define QSTR 36     // attention Q/K/V row stride
#define ASTR 36     // alpha (transposed [j][i]) row stride
#define AHD  1152   // alpha head stride (32*36)
#define CSTR 33     // multiplicity row stride (scalar conflict-free)

typedef unsigned long long ull;

struct Smem {
    float WA[4608];   // weights [m][WSTR] -> alphaT [hd][j][i]; attn Wq/Wk/Wv^T
    float H[2176];    // GAT h [j][68]; attn Q/K/V stride 36; pool scratch
    float X[2176];    // activations [i][68]
    float C[1056];    // multiplicity [i][33]
    float ES[128], ED[128];
    float AS[64], AD[64], B[64];
};

// ---------- f32x2 helpers (attention phase) ----------
__device__ __forceinline__ void fma2(ull& acc, ull a, ull b) {
    asm("fma.rn.f32x2 %0, %1, %2, %0;" : "+l"(acc) : "l"(a), "l"(b));
}
__device__ __forceinline__ float red2(ull v) {
    float lo, hi;
    asm("mov.b64 {%0,%1}, %2;" : "=f"(lo), "=f"(hi) : "l"(v));
    return lo + hi;
}
__device__ __forceinline__ ulonglong2 ld2(const float* p) { return *(const ulonglong2*)p; }
__device__ __forceinline__ float lrelu(float v, float s) { return v > 0.f ? v : v * s; }

// ---------- tf32 split: hi = rna(f) (exactly representable), lo = f - hi (exact FSUB).
// lo is passed RAW to the mma; its own hw rounding costs ~2^-22*|f| -> negligible.
struct TF2 { uint32_t hi, lo; };
__device__ __forceinline__ TF2 tf32x(float f) {
    TF2 r;
    asm("cvt.rna.tf32.f32 %0, %1;" : "=r"(r.hi) : "f"(f));
    r.lo = __float_as_uint(f - __uint_as_float(r.hi));
    return r;
}
__device__ __forceinline__ void mma8(float* d, const uint32_t* a, const uint32_t* b) {
    asm("mma.sync.aligned.m16n8k8.row.col.f32.tf32.tf32.f32 "
        "{%0,%1,%2,%3}, {%4,%5,%6,%7}, {%8,%9}, {%0,%1,%2,%3};"
        : "+f"(d[0]), "+f"(d[1]), "+f"(d[2]), "+f"(d[3])
        : "r"(a[0]), "r"(a[1]), "r"(a[2]), "r"(a[3]), "r"(b[0]), "r"(b[1]));
}
__device__ __forceinline__ void mma3x(float* d, const TF2* a, const TF2* b) {
    uint32_t ah[4] = {a[0].hi, a[1].hi, a[2].hi, a[3].hi};
    uint32_t al[4] = {a[0].lo, a[1].lo, a[2].lo, a[3].lo};
    uint32_t bh[2] = {b[0].hi, b[1].hi};
    uint32_t bl[2] = {b[0].lo, b[1].lo};
    mma8(d, al, bh);
    mma8(d, ah, bl);
    mma8(d, ah, bh);
}

template<int CIN, int CINP, int H4>
__device__ void gat_layer(Smem& s,
                          const float* __restrict__ W, const float* __restrict__ as_,
                          const float* __restrict__ ad_, const float* __restrict__ b_,
                          int tid)
{
    const int lane = tid & 31;
    const int w    = tid >> 5;     // warp 0..3, owns cols 16w..16w+15 (= head w for H4=4)
    const int g    = lane >> 2;    // 0..7
    const int t4   = lane & 3;     // 0..3

    __syncthreads();   // prior X writes / prior alphaT (in WA) reads complete

    // ---- stage W [m][k] natural layout, zero-pad rows to CINP ----
    for (int idx = tid; idx < CINP * 16; idx += 128) {
        int m = idx >> 4, c4 = (idx & 15) * 4;
        float4 v = (m < CIN) ? *(const float4*)&W[m * 64 + c4]
                             : make_float4(0.f, 0.f, 0.f, 0.f);
        *(float4*)&s.WA[m * WSTR + c4] = v;
    }
    if (tid < 64) { s.AS[tid] = as_[tid]; s.AD[tid] = ad_[tid]; s.B[tid] = b_[tid]; }
    __syncthreads();

    // ---- mm1: H = X @ W  (warp w -> 16 cols), 3xTF32 ----
    float d[2][2][4] = {};
#pragma unroll
    for (int st = 0; st < CINP / 8; st++) {
        const int m0 = 8 * st;
        TF2 a[2][4], b[2][2];
#pragma unroll
        for (int ti = 0; ti < 2; ti++) {
            int r0 = 16 * ti + g;
            a[ti][0] = tf32x(s.X[r0 * XSTR + m0 + t4]);
            a[ti][1] = tf32x(s.X[(r0 + 8) * XSTR + m0 + t4]);
            a[ti][2] = tf32x(s.X[r0 * XSTR + m0 + t4 + 4]);
            a[ti][3] = tf32x(s.X[(r0 + 8) * XSTR + m0 + t4 + 4]);
        }
#pragma unroll
        for (int nt = 0; nt < 2; nt++) {
            int col = 16 * w + 8 * nt + g;
            b[nt][0] = tf32x(s.WA[(m0 + t4) * WSTR + col]);
            b[nt][1] = tf32x(s.WA[(m0 + t4 + 4) * WSTR + col]);
        }
#pragma unroll
        for (int ti = 0; ti < 2; ti++)
#pragma unroll
            for (int nt = 0; nt < 2; nt++)
                mma3x(d[ti][nt], a[ti], b[nt]);
    }

    // ---- e_s/e_d partials straight from D-fragments ----
    {
        float esp[4] = {0.f, 0.f, 0.f, 0.f}, edp[4] = {0.f, 0.f, 0.f, 0.f};
#pragma unroll
        for (int ti = 0; ti < 2; ti++)
#pragma unroll
            for (int nt = 0; nt < 2; nt++) {
                int cb = 16 * w + 8 * nt + 2 * t4;
                float s0 = s.AS[cb], s1 = s.AS[cb + 1];
                float a0 = s.AD[cb], a1 = s.AD[cb + 1];
                esp[2 * ti]     += d[ti][nt][0] * s0 + d[ti][nt][1] * s1;
                esp[2 * ti + 1] += d[ti][nt][2] * s0 + d[ti][nt][3] * s1;
                edp[2 * ti]     += d[ti][nt][0] * a0 + d[ti][nt][1] * a1;
                edp[2 * ti + 1] += d[ti][nt][2] * a0 + d[ti][nt][3] * a1;
            }
#pragma unroll
        for (int m = 1; m <= 2; m <<= 1)
#pragma unroll
            for (int r = 0; r < 4; r++) {
                esp[r] += __shfl_xor_sync(0xFFFFFFFF, esp[r], m);
                edp[r] += __shfl_xor_sync(0xFFFFFFFF, edp[r], m);
            }
        if (t4 == 0) {
#pragma unroll
            for (int r = 0; r < 4; r++) {
                int row = 16 * (r >> 1) + 8 * (r & 1) + g;
                s.ES[w * 32 + row] = esp[r];
                s.ED[w * 32 + row] = edp[r];
            }
        }
    }

    // ---- store H fragments [j][k] ----
#pragma unroll
    for (int ti = 0; ti < 2; ti++)
#pragma unroll
        for (int nt = 0; nt < 2; nt++) {
            int r0 = 16 * ti + g, col = 16 * w + 8 * nt + 2 * t4;
            *(float2*)&s.H[r0 * HSTR + col]       = make_float2(d[ti][nt][0], d[ti][nt][1]);
            *(float2*)&s.H[(r0 + 8) * HSTR + col] = make_float2(d[ti][nt][2], d[ti][nt][3]);
        }

    if (H4 == 1) {
        __syncthreads();
        if (tid < 32) {
            s.ES[tid] = s.ES[tid] + s.ES[32 + tid] + s.ES[64 + tid] + s.ES[96 + tid];
            s.ED[tid] = s.ED[tid] + s.ED[32 + tid] + s.ED[64 + tid] + s.ED[96 + tid];
        }
        __syncthreads();
    } else {
        __syncwarp();
    }

    // ---- masked multiplicity-weighted softmax; alphaT[j][i] -> WA ----
    if (tid < 32 * H4) {
        const int i = tid & 31, hd = tid >> 5;
        const float edi = s.ED[hd * 32 + i];
        const float* esr = &s.ES[hd * 32];
        const float* crow = &s.C[i * CSTR];
        float ev[32];
        float mx = -1e30f;
#pragma unroll
        for (int j = 0; j < 32; j++) {
            float e = lrelu(esr[j] + edi, 0.2f);
            ev[j] = e;
            if (crow[j] > 0.f && e > mx) mx = e;
        }
        float den = 0.f;
#pragma unroll
        for (int j = 0; j < 32; j++) {
            float wv = crow[j] * __expf(ev[j] - mx);
            ev[j] = wv; den += wv;
        }
        float inv = 1.f / (den + 1e-16f);
        float* at0 = &s.WA[hd * AHD];
#pragma unroll
        for (int j = 0; j < 32; j++)
            at0[j * ASTR + i] = ev[j] * inv;     // transposed, conflict-free
    }
    if (H4 == 1) __syncthreads(); else __syncwarp();

    // ---- mm2: X[i][col] = lrelu( alpha_hd @ H + b ), 3xTF32 ----
    {
        const int hd = (H4 == 4) ? w : 0;
        const float* AT = &s.WA[hd * AHD];
        float d2[2][2][4] = {};
#pragma unroll
        for (int st = 0; st < 4; st++) {
            const int j0 = 8 * st;
            TF2 a[2][4], b[2][2];
#pragma unroll
            for (int ti = 0; ti < 2; ti++) {
                int r0 = 16 * ti + g;
                a[ti][0] = tf32x(AT[(j0 + t4) * ASTR + r0]);
                a[ti][1] = tf32x(AT[(j0 + t4) * ASTR + r0 + 8]);
                a[ti][2] = tf32x(AT[(j0 + t4 + 4) * ASTR + r0]);
                a[ti][3] = tf32x(AT[(j0 + t4 + 4) * ASTR + r0 + 8]);
            }
#pragma unroll
            for (int nt = 0; nt < 2; nt++) {
                int col = 16 * w + 8 * nt + g;
                b[nt][0] = tf32x(s.H[(j0 + t4) * HSTR + col]);
                b[nt][1] = tf32x(s.H[(j0 + t4 + 4) * HSTR + col]);
            }
#pragma unroll
            for (int ti = 0; ti < 2; ti++)
#pragma unroll
                for (int nt = 0; nt < 2; nt++)
                    mma3x(d2[ti][nt], a[ti], b[nt]);
        }
#pragma unroll
        for (int ti = 0; ti < 2; ti++)
#pragma unroll
            for (int nt = 0; nt < 2; nt++) {
                int r0 = 16 * ti + g, col = 16 * w + 8 * nt + 2 * t4;
                float b0 = s.B[col], b1 = s.B[col + 1];
                *(float2*)&s.X[r0 * XSTR + col] =
                    make_float2(lrelu(d2[ti][nt][0] + b0, 0.01f), lrelu(d2[ti][nt][1] + b1, 0.01f));
                *(float2*)&s.X[(r0 + 8) * XSTR + col] =
                    make_float2(lrelu(d2[ti][nt][2] + b0, 0.01f), lrelu(d2[ti][nt][3] + b1, 0.01f));
            }
    }
}

__global__ __launch_bounds__(128, 5) void gnn_kernel(
    const float* __restrict__ x, const int* __restrict__ ei,
    const float* __restrict__ Wq, const float* __restrict__ Wk, const float* __restrict__ Wv,
    const float* __restrict__ W1, const float* __restrict__ a1s, const float* __restrict__ a1d, const float* __restrict__ b1,
    const float* __restrict__ W2, const float* __restrict__ a2s, const float* __restrict__ a2d, const float* __restrict__ b2,
    const float* __restrict__ W3, const float* __restrict__ a3s, const float* __restrict__ a3d, const float* __restrict__ b3,
    const float* __restrict__ W4, const float* __restrict__ a4s, const float* __restrict__ a4d, const float* __restrict__ b4,
    const float* __restrict__ fcW, const float* __restrict__ fcb,
    float* __restrict__ out, int out_half)
{
    __shared__ Smem s;
    const int tid = threadIdx.x;
    const int g = blockIdx.x;

    const bool is64 = (ei[2 * (size_t)EDGES_TOTAL - 1] == 0);

    // ---------------- Attention layer (f32 FFMA2 path) ----------------
    // P1: Wq/Wk/Wv transposed into WA [c][i] stride QSTR; lanes i-low(4) x c-low(8)
    {
        const int il = tid & 3;
        const int cl = (tid >> 2) & 7;
        const int ih = tid >> 5;
#pragma unroll
        for (int e = 0; e < 24; e++) {
            int which = e >> 3, f = e & 7;
            int i = il + 4 * ih + 16 * (f & 1);
            int c = cl + 8 * ((f >> 1) & 1) + 16 * (f >> 2);
            const float* Wsrc = (which == 0) ? Wq : (which == 1) ? Wk : Wv;
            s.WA[which * 1280 + c * QSTR + i] = Wsrc[i * 32 + c];
        }
    }
    for (int t = tid; t < 320; t += 128) {
        int si = t >> 5, ii = t & 31;
        s.C[si * 32 + ii] = x[(size_t)(g * 32 + ii) * FEAT + si];
    }
    __syncthreads();

    // P2: Q,K,V [s][c] stride 36 -> H at 0/360/720
    for (int o = tid; o < 960; o += 128) {
        int which = o / 320, r = o - which * 320;
        int si = r >> 5, c = r & 31;
        const float* wt = &s.WA[which * 1280 + c * QSTR];
        const float* at = &s.C[si * 32];
        ull acc = 0;
#pragma unroll
        for (int ig = 0; ig < 32; ig += 4) {
            ulonglong2 a2 = ld2(at + ig), w2 = ld2(wt + ig);
            fma2(acc, a2.x, w2.x); fma2(acc, a2.y, w2.y);
        }
        s.H[which * 360 + si * 36 + c] = red2(acc);
    }
    __syncthreads();

    // P3: scores [s][t] -> ES; zero C
    for (int t = tid; t < NODES * CSTR; t += 128) s.C[t] = 0.f;
    if (tid < 100) {
        int si = tid / 10, ti = tid - si * 10;
        ull acc = 0;
#pragma unroll
        for (int cg = 0; cg < 32; cg += 4) {
            ulonglong2 q2 = ld2(&s.H[si * 36 + cg]);
            ulonglong2 k2 = ld2(&s.H[360 + ti * 36 + cg]);
            fma2(acc, q2.x, k2.x); fma2(acc, q2.y, k2.y);
        }
        s.ES[si * 10 + ti] = red2(acc);
    }
    __syncthreads();

    // P4: multiplicity matrix + attention row softmax
#pragma unroll
    for (int half = 0; half < 2; half++) {
        size_t eg = (size_t)g * EPG + tid + 128 * half;
        int srcv, dstv;
        if (is64) {
            srcv = ei[2 * eg];
            dstv = ei[2 * ((size_t)EDGES_TOTAL + eg)];
        } else {
            srcv = ei[eg];
            dstv = ei[(size_t)EDGES_TOTAL + eg];
        }
        int sl = srcv - g * 32, dl = dstv - g * 32;
        atomicAdd(&s.C[dl * CSTR + sl], 1.0f);
    }
    if (tid < 32) atomicAdd(&s.C[tid * CSTR + tid], 1.0f);  // self-loops
    if (tid < 10) {
        float mx = -1e30f;
#pragma unroll
        for (int t2 = 0; t2 < 10; t2++) mx = fmaxf(mx, s.ES[tid * 10 + t2]);
        float e[10], sum = 0.f;
#pragma unroll
        for (int t2 = 0; t2 < 10; t2++) { e[t2] = __expf(s.ES[tid * 10 + t2] - mx); sum += e[t2]; }
        float inv = 1.f / sum;
#pragma unroll
        for (int t2 = 0; t2 < 10; t2++) s.ES[tid * 10 + t2] = e[t2] * inv;
    }
    __syncthreads();

    // P5: att out[s][i] -> X[i][s]; zero pad cols 10..15
    for (int t = tid; t < 320; t += 128) {
        int si = t >> 5, ii = t & 31;
        float acc = 0.f;
#pragma unroll
        for (int t2 = 0; t2 < 10; t2++)
            acc += s.ES[si * 10 + t2] * s.H[720 + t2 * 36 + ii];
        s.X[ii * XSTR + si] = acc;
    }
    for (int t = tid; t < 192; t += 128) {
        int ii = t & 31, cc = 10 + (t >> 5);
        s.X[ii * XSTR + cc] = 0.f;
    }

    // ---------------- GAT stack (tensor-core 3xTF32) ----------------
    gat_layer<10, 16, 4>(s, W1, a1s, a1d, b1, tid);
    gat_layer<64, 64, 4>(s, W2, a2s, a2d, b2, tid);
    gat_layer<64, 64, 4>(s, W3, a3s, a3d, b3, tid);
    gat_layer<64, 64, 1>(s, W4, a4s, a4d, b4, tid);
    __syncthreads();

    // ---------------- Mean pool + FC + softmax ----------------
    if (tid < 64) {
        float acc = 0.f;
#pragma unroll
        for (int i = 0; i < 32; i++) acc += s.X[i * XSTR + tid];
        s.H[tid] = acc * (1.f / 32.f);
    }
    __syncthreads();
    if (tid < 2) {
        float acc = fcb[tid];
#pragma unroll
        for (int k2 = 0; k2 < 64; k2++) acc += s.H[k2] * fcW[k2 * 2 + tid];
        s.ED[tid] = acc;
    }
    __syncthreads();
    if (tid == 0) {
        float l0 = s.ED[0], l1 = s.ED[1];
        out[g * 2 + 0] = l0;
        out[g * 2 + 1] = l1;
        float mx = fmaxf(l0, l1);
        float e0 = __expf(l0 - mx), e1 = __expf(l1 - mx);
        float inv = 1.f / (e0 + e1);
        out[out_half + g * 2 + 0] = e0 * inv;
        out[out_half + g * 2 + 1] = e1 * inv;
    }
}

extern "C" void kernel_launch(void* const* d_in, const int* in_sizes, int n_in,
                              void* d_out, int out_size)
{
    const float* x   = (const float*)d_in[0];
    const int*   ei  = (const int*)d_in[1];
    const float* Wq  = (const float*)d_in[3];
    const float* Wk  = (const float*)d_in[4];
    const float* Wv  = (const float*)d_in[5];
    const float* W1  = (const float*)d_in[6];
    const float* a1s = (const float*)d_in[7];
    const float* a1d = (const float*)d_in[8];
    const float* b1  = (const float*)d_in[9];
    const float* W2  = (const float*)d_in[10];
    const float* a2s = (const float*)d_in[11];
    const float* a2d = (const float*)d_in[12];
    const float* b2  = (const float*)d_in[13];
    const float* W3  = (const float*)d_in[14];
    const float* a3s = (const float*)d_in[15];
    const float* a3d = (const float*)d_in[16];
    const float* b3  = (const float*)d_in[17];
    const float* W4  = (const float*)d_in[18];
    const float* a4s = (const float*)d_in[19];
    const float* a4d = (const float*)d_in[20];
    const float* b4  = (const float*)d_in[21];
    const float* fcW = (const float*)d_in[22];
    const float* fcb = (const float*)d_in[23];

    gnn_kernel<<<NGRAPH, 128>>>(x, ei, Wq, Wk, Wv,
                                W1, a1s, a1d, b1,
                                W2, a2s, a2d, b2,
                                W3, a3s, a3d, b3,
                                W4, a4s, a4d, b4,
                                fcW, fcb,
                                (float*)d_out, out_size / 2);
}